// round 11
// baseline (speedup 1.0000x reference)
#include <cuda_runtime.h>
#include <math.h>

#define BB 8
#define SEQ 4096
#define DM 1024
#define NS 64
#define SCH 64          // scan steps per smem chunk
#define CHUNK 512       // sequence chunk per CTA (parallel-in-time)
#define WARM 64         // warmup steps (state error <= 0.7311^64 ~ 2e-9)
#define NCHUNK (SEQ / CHUNK)

typedef unsigned long long u64;
typedef unsigned int u32;

// ---------------- static scratch (no allocations allowed) ----------------
__device__ __align__(16) float g_Bs[NS * DM];              // sigmoid(B_w), [N, D]
__device__ __align__(16) float g_Aperm[DM * NS];           // sigmoid(A_raw), permuted n
__device__ __align__(16) float g_Cperm[DM * NS];           // sigmoid(C_w), permuted n
__device__ __align__(16) float g_g[DM];                    // sigmoid(gamma)
__device__ __align__(16) float g_sumC[DM];                 // sum_n sigmoid(C_w[d,n])
__device__ __align__(16) float g_U[(size_t)BB * SEQ * NS]; // X @ Bm^T, permuted n
__device__ __align__(16) float g_umin[(size_t)BB * SEQ];   // min_n U[b,s,n]

__device__ __forceinline__ float sigmoidf_(float v) {
    return 1.0f / (1.0f + expf(-v));
}

// ---------------- packed f32x2 helpers ----------------
__device__ __forceinline__ u64 pack2(float lo, float hi) {
    u64 r;
    asm("mov.b64 %0, {%1, %2};" : "=l"(r) : "f"(lo), "f"(hi));
    return r;
}
__device__ __forceinline__ void unpack2(u64 v, float& lo, float& hi) {
    asm("mov.b64 {%0, %1}, %2;" : "=f"(lo), "=f"(hi) : "l"(v));
}
__device__ __forceinline__ u64 fma2_(u64 a, u64 b, u64 c) {
    u64 r;
    asm("fma.rn.f32x2 %0, %1, %2, %3;" : "=l"(r) : "l"(a), "l"(b), "l"(c));
    return r;
}

// State update, one pair: h = min(1, h*A + u*x). Lower clip provably dead
// (u>=0, x>=0, A>0, h0=0 => h*A+u*x >= 0). min on ALU pipe.
__device__ __forceinline__ void step_pair(float& h0, float& h1, u64 u2, u64 xp, u64 a2) {
    asm("{\n\t"
        ".reg .b64 t, hp;\n\t"
        "mul.rn.f32x2 t, %2, %3;\n\t"
        "mov.b64 hp, {%0, %1};\n\t"
        "fma.rn.f32x2 hp, hp, %4, t;\n\t"
        "mov.b64 {%0, %1}, hp;\n\t"
        "}\n\t"
        : "+f"(h0), "+f"(h1) : "l"(u2), "l"(xp), "l"(a2));
    h0 = fminf(h0, 1.0f);
    h1 = fminf(h1, 1.0f);
}

__device__ __forceinline__ void dot_pair(u64& p2, float h0, float h1, u64 c2) {
    asm("{\n\t"
        ".reg .b64 hp;\n\t"
        "mov.b64 hp, {%1, %2};\n\t"
        "fma.rn.f32x2 %0, hp, %3, %0;\n\t"
        "}\n\t"
        : "+l"(p2) : "f"(h0), "f"(h1), "l"(c2));
}

// permutation: state n -> storage position, lane lp=n%4 owns n = lp + 4j,
// stored at lp*16 + j so each lane reads 16 contiguous floats (4x LDG.128)
__device__ __forceinline__ int permn(int n) { return ((n & 3) << 4) | (n >> 2); }

// ---------------- kernel 1: precompute sigmoids ----------------
__global__ void prep_kernel(const float* __restrict__ A_raw,
                            const float* __restrict__ B_w,
                            const float* __restrict__ C_w,
                            const float* __restrict__ gamma) {
    int i = blockIdx.x * 256 + threadIdx.x;
    if (i < NS * DM) {
        g_Bs[i] = sigmoidf_(B_w[i]);           // B_w is [N, D]
        int d = i >> 6, n = i & 63;            // A_raw / C_w are [D, N]
        int p = permn(n);
        g_Aperm[(d << 6) + p] = sigmoidf_(A_raw[i]);
        g_Cperm[(d << 6) + p] = sigmoidf_(C_w[i]);
    }
    if (i < DM) {
        g_g[i] = sigmoidf_(gamma[i]);
        float s = 0.0f;
        for (int n = 0; n < NS; n++) s += sigmoidf_(C_w[i * NS + n]);
        g_sumC[i] = s;    // y_d when all 64 states saturate at 1.0
    }
}

// ---------------- kernel 2: U = X @ Bs^T + fused umin ----------------
// 64 rows x 64 cols per block, 128 threads, thread = 8 rows x 4 cols.
// Smem holds X as row-pairs (x_r, x_{r+1}) and B pre-duplicated (w, w):
// inner loop is pure LDS.128 + FFMA2, no packing.
__global__ void __launch_bounds__(128) gemm_kernel(const float* __restrict__ X) {
    __shared__ __align__(16) u64 Xs2[32][34];  // [k][row-pair 0..31], pad 2
    __shared__ __align__(16) u64 Wd[32][66];   // [k][n dup], pad 2
    int tid = threadIdx.x;
    int row0 = blockIdx.x * 64;
    int tx = tid & 15, ty = tid >> 4;          // ty 0..7 -> rows ty*8..+7
    u64 acc[4][4];
#pragma unroll
    for (int p = 0; p < 4; p++)
#pragma unroll
        for (int j = 0; j < 4; j++) acc[p][j] = 0ull;

    for (int k0 = 0; k0 < DM; k0 += 32) {
        __syncthreads();
#pragma unroll
        for (int i = 0; i < 4; i++) {          // X: 64 rows x 32 k = 512 f4
            int idx = tid + (i << 7);
            int r = idx >> 3, q = idx & 7;
            float4 v = *(const float4*)(X + (size_t)(row0 + r) * DM + k0 + (q << 2));
            float* dst0 = (float*)&Xs2[q * 4 + 0][r >> 1] + (r & 1);
            dst0[0] = v.x;
            ((float*)&Xs2[q * 4 + 1][r >> 1])[r & 1] = v.y;
            ((float*)&Xs2[q * 4 + 2][r >> 1])[r & 1] = v.z;
            ((float*)&Xs2[q * 4 + 3][r >> 1])[r & 1] = v.w;
        }
#pragma unroll
        for (int i = 0; i < 4; i++) {          // W: 64 n x 32 k = 512 f4
            int idx = tid + (i << 7);
            int n = idx >> 3, q = idx & 7;
            float4 w = *(const float4*)(g_Bs + (size_t)n * DM + k0 + (q << 2));
            Wd[q * 4 + 0][n] = pack2(w.x, w.x);
            Wd[q * 4 + 1][n] = pack2(w.y, w.y);
            Wd[q * 4 + 2][n] = pack2(w.z, w.z);
            Wd[q * 4 + 3][n] = pack2(w.w, w.w);
        }
        __syncthreads();
#pragma unroll
        for (int k = 0; k < 32; k++) {
            ulonglong2 xa = *(const ulonglong2*)&Xs2[k][ty * 4];
            ulonglong2 xb = *(const ulonglong2*)&Xs2[k][ty * 4 + 2];
            ulonglong2 wa = *(const ulonglong2*)&Wd[k][tx * 4];
            ulonglong2 wb = *(const ulonglong2*)&Wd[k][tx * 4 + 2];
            u64 xp[4] = {xa.x, xa.y, xb.x, xb.y};
            u64 wd[4] = {wa.x, wa.y, wb.x, wb.y};
#pragma unroll
            for (int p = 0; p < 4; p++)
#pragma unroll
                for (int j = 0; j < 4; j++) acc[p][j] = fma2_(xp[p], wd[j], acc[p][j]);
        }
    }

    // epilogue: store U (permuted) + fused row-min reduction -> g_umin
    float rmin[8];
#pragma unroll
    for (int t = 0; t < 8; t++) rmin[t] = 3.4e38f;
#pragma unroll
    for (int p = 0; p < 4; p++) {
        int rlo = row0 + ty * 8 + 2 * p;
#pragma unroll
        for (int j = 0; j < 4; j++) {
            float lo, hi;
            unpack2(acc[p][j], lo, hi);
            int pc = permn(tx * 4 + j);
            g_U[(size_t)rlo * NS + pc] = lo;
            g_U[(size_t)(rlo + 1) * NS + pc] = hi;
            rmin[2 * p] = fminf(rmin[2 * p], lo);
            rmin[2 * p + 1] = fminf(rmin[2 * p + 1], hi);
        }
    }
#pragma unroll
    for (int t = 0; t < 8; t++) {
#pragma unroll
        for (int o = 1; o < 16; o <<= 1)
            rmin[t] = fminf(rmin[t], __shfl_xor_sync(0xffffffffu, rmin[t], o, 16));
    }
    if (tx == 0) {
#pragma unroll
        for (int t = 0; t < 8; t++)
            g_umin[row0 + ty * 8 + t] = rmin[t];
    }
}

// ---------------- kernel 3 helpers: slow step ----------------
template <bool WRITE_Y>
__device__ __forceinline__ void slow_step(
    int b, int s, const float* __restrict__ xs, float* __restrict__ ys,
    float* h, int sl, int d, int lp, int dloc) {
    float xv = xs[(sl << 5) + dloc];
    const ulonglong2* up = (const ulonglong2*)(
        g_U + (((size_t)b * SEQ + s) << 6) + (lp << 4));
    ulonglong2 u0 = up[0], u1 = up[1], u2 = up[2], u3 = up[3];
    const ulonglong2* ap = (const ulonglong2*)(
        g_Aperm + ((size_t)d << 6) + (lp << 4));
    ulonglong2 a0 = ap[0], a1 = ap[1], a2 = ap[2], a3 = ap[3];
    u64 xp = pack2(xv, xv);
    step_pair(h[0],  h[1],  u0.x, xp, a0.x);
    step_pair(h[2],  h[3],  u0.y, xp, a0.y);
    step_pair(h[4],  h[5],  u1.x, xp, a1.x);
    step_pair(h[6],  h[7],  u1.y, xp, a1.y);
    step_pair(h[8],  h[9],  u2.x, xp, a2.x);
    step_pair(h[10], h[11], u2.y, xp, a2.y);
    step_pair(h[12], h[13], u3.x, xp, a3.x);
    step_pair(h[14], h[15], u3.y, xp, a3.y);
    if (WRITE_Y) {
        const ulonglong2* cp = (const ulonglong2*)(
            g_Cperm + ((size_t)d << 6) + (lp << 4));
        ulonglong2 c0 = cp[0], c1 = cp[1], c2 = cp[2], c3 = cp[3];
        u64 p2 = 0ull;
        dot_pair(p2, h[0],  h[1],  c0.x);
        dot_pair(p2, h[2],  h[3],  c0.y);
        dot_pair(p2, h[4],  h[5],  c1.x);
        dot_pair(p2, h[6],  h[7],  c1.y);
        dot_pair(p2, h[8],  h[9],  c2.x);
        dot_pair(p2, h[10], h[11], c2.y);
        dot_pair(p2, h[12], h[13], c3.x);
        dot_pair(p2, h[14], h[15], c3.y);
        float plo, phi;
        unpack2(p2, plo, phi);
        float p = plo + phi;
        p += __shfl_xor_sync(0xffffffffu, p, 1, 4);
        p += __shfl_xor_sync(0xffffffffu, p, 2, 4);
        if (lp == 0) ys[(sl << 5) + dloc] = p;
    }
}

// ---------------- kernel 3: chunked scan with staged saturation mask ----
// grid (D/32, NCHUNK, B), block 128. Warp owns 8 d's (4 lanes each), lane
// owns 16 n-states. Saturation (x*umin >= 1 forces ALL states of a d to
// exactly 1.0: RN monotone, h*A >= 0) is evaluated during staging from
// registers into a per-warp 64-bit mask; ys is prefilled with sumC. The
// scan phase touches only the slow bits (~3%) via __ffs.
__global__ void __launch_bounds__(128) scan_kernel(const float* __restrict__ X,
                                                   float* __restrict__ Y,
                                                   float* __restrict__ Hout) {
    __shared__ __align__(16) float xs[SCH * 32];   // x chunk [sl][dloc]
    __shared__ __align__(16) float ys[SCH * 32];   // y chunk (pre-normalization)
    __shared__ u32 smask[8];                       // [warp][2]: bit sl = all-8-d sat

    int b = blockIdx.z;
    int c = blockIdx.y;
    int dbase = blockIdx.x << 5;
    int tid = threadIdx.x;
    int warp = tid >> 5, lane = tid & 31;
    int grp = lane >> 2, lp = lane & 3;
    int dloc = (warp << 3) | grp;    // 0..31
    int d = dbase + dloc;
    int qme = tid & 7;               // staging column group (fixed across i)

    float h[16];
    bool ones = false;
#pragma unroll
    for (int j = 0; j < 16; j++) h[j] = 0.0f;
    float4 sumC4 = *(const float4*)(g_sumC + dbase + (qme << 2));

    const size_t xbase = (size_t)b * SEQ * DM;
    const int s_out0 = c * CHUNK;
    const int s_begin = (c == 0) ? 0 : s_out0 - WARM;
    const int s_end = s_out0 + CHUNK;

    for (int s0 = s_begin; s0 < s_end; s0 += SCH) {
        bool writey = (s0 >= s_out0);
        __syncthreads();                       // prev chunk fully consumed
        if (tid < 8) smask[tid] = 0xFFFFFFFFu;

        float4 xv4[4];
        bool bb[4];
#pragma unroll
        for (int i = 0; i < 4; i++) {          // load + test in registers
            int idx = tid + (i << 7);
            int sl = idx >> 3;
            xv4[i] = *(const float4*)(X + xbase + (size_t)(s0 + sl) * DM +
                                      dbase + (qme << 2));
            float um = __ldg(g_umin + (size_t)b * SEQ + s0 + sl);
            bb[i] = (xv4[i].x * um >= 1.0f) & (xv4[i].y * um >= 1.0f) &
                    (xv4[i].z * um >= 1.0f) & (xv4[i].w * um >= 1.0f);
        }
        __syncthreads();                       // smask init visible
#pragma unroll
        for (int i = 0; i < 4; i++) {
            int idx = tid + (i << 7);
            int sl = idx >> 3;
            ((float4*)xs)[idx] = xv4[i];
            if (writey) ((float4*)ys)[idx] = sumC4;
            if (!bb[i])
                atomicAnd(&smask[((qme >> 1) << 1) + (sl >> 5)], ~(1u << (sl & 31)));
        }
        __syncthreads();                       // masks + xs + prefill visible

        u32 sat0 = smask[warp * 2], sat1 = smask[warp * 2 + 1];
        u32 w0 = ~sat0, w1 = ~sat1;
        while (w0) {
            int sl = __ffs(w0) - 1;
            w0 &= w0 - 1;
            bool ps = sl ? ((sat0 >> (sl - 1)) & 1u) : ones;
            if (ps) {
#pragma unroll
                for (int j = 0; j < 16; j++) h[j] = 1.0f;
            }
            if (writey) slow_step<true>(b, s0 + sl, xs, ys, h, sl, d, lp, dloc);
            else        slow_step<false>(b, s0 + sl, xs, ys, h, sl, d, lp, dloc);
        }
        while (w1) {
            int t = __ffs(w1) - 1;
            w1 &= w1 - 1;
            int sl = 32 + t;
            bool ps = t ? ((sat1 >> (t - 1)) & 1u) : ((sat0 >> 31) & 1u);
            if (ps) {
#pragma unroll
                for (int j = 0; j < 16; j++) h[j] = 1.0f;
            }
            if (writey) slow_step<true>(b, s0 + sl, xs, ys, h, sl, d, lp, dloc);
            else        slow_step<false>(b, s0 + sl, xs, ys, h, sl, d, lp, dloc);
        }
        ones = ((sat1 >> 31) & 1u) != 0;

        if (writey) {
            __syncthreads();
            // dump y chunk (coalesced) into d_out's y region
#pragma unroll
            for (int i = 0; i < 4; i++) {
                int idx = tid + (i << 7);
                int sl = idx >> 3, q = idx & 7;
                *(float4*)(Y + ((size_t)b * SEQ + s0 + sl) * DM + dbase + (q << 2)) =
                    ((float4*)ys)[idx];
            }
        }
    }

    if (Hout && c == NCHUNK - 1) {   // h_final [B, D, N], lane lp owns n = lp + 4j
#pragma unroll
        for (int j = 0; j < 16; j++) {
            float hv = ones ? 1.0f : h[j];
            Hout[(((size_t)b * DM + d) << 6) + lp + (j << 2)] = hv;
        }
    }
}

// ---------------- kernel 4: normalize + residual + clip (in place) -------
__global__ void __launch_bounds__(256) finalize_kernel(const float* __restrict__ X,
                                                       float* __restrict__ out) {
    size_t row = blockIdx.x;   // b*SEQ + s
    int tid = threadIdx.x;
    float4 v = ((const float4*)(out + row * DM))[tid];
    float ps = v.x + v.y + v.z + v.w;
#pragma unroll
    for (int o = 16; o; o >>= 1) ps += __shfl_xor_sync(0xffffffffu, ps, o);
    __shared__ float wsum[8];
    if ((tid & 31) == 0) wsum[tid >> 5] = ps;
    __syncthreads();
    float tot = 0.0f;
#pragma unroll
    for (int w = 0; w < 8; w++) tot += wsum[w];
    float inv = 1.0f / (tot + 1e-6f);
    float4 xv = ((const float4*)(X + row * DM))[tid];
    float4 gv = ((const float4*)g_g)[tid];
    float4 r;
    r.x = __saturatef(fmaf(v.x * gv.x, inv, xv.x));
    r.y = __saturatef(fmaf(v.y * gv.y, inv, xv.y));
    r.z = __saturatef(fmaf(v.z * gv.z, inv, xv.z));
    r.w = __saturatef(fmaf(v.w * gv.w, inv, xv.w));
    ((float4*)(out + row * DM))[tid] = r;
}

// ---------------- launch ----------------
extern "C" void kernel_launch(void* const* d_in, const int* in_sizes, int n_in,
                              void* d_out, int out_size) {
    const float* x     = (const float*)d_in[0];
    const float* A_raw = (const float*)d_in[1];
    const float* B_w   = (const float*)d_in[2];
    const float* C_w   = (const float*)d_in[3];
    const float* gamma = (const float*)d_in[4];
    float* out = (float*)d_out;

    const size_t Y_ELEMS = (size_t)BB * SEQ * DM;       // 33,554,432
    const size_t H_ELEMS = (size_t)BB * DM * NS;        // 524,288
    float* hout = ((size_t)out_size >= Y_ELEMS + H_ELEMS) ? (out + Y_ELEMS) : nullptr;

    prep_kernel<<<256, 256>>>(A_raw, B_w, C_w, gamma);
    gemm_kernel<<<(BB * SEQ) / 64, 128>>>(x);
    scan_kernel<<<dim3(DM / 32, NCHUNK, BB), 128>>>(x, out, hout);
    finalize_kernel<<<BB * SEQ, 256>>>(x, out);
}

// round 12
// speedup vs baseline: 1.1071x; 1.1071x over previous
#include <cuda_runtime.h>
#include <cuda_bf16.h>
#include <math.h>

#define BB 8
#define SEQ 4096
#define DM 1024
#define NS 64
#define SCH 64          // scan steps per smem chunk
#define CHUNK 512       // sequence chunk per CTA (parallel-in-time)
#define WARM 64         // warmup steps (state error <= 0.7311^64 ~ 2e-9)
#define NCHUNK (SEQ / CHUNK)

typedef unsigned long long u64;
typedef unsigned int u32;

// ---------------- static scratch (no allocations allowed) ----------------
__device__ __align__(16) float g_Bs[NS * DM];              // sigmoid(B_w), [N, D]
__device__ __align__(16) float g_Aperm[DM * NS];           // sigmoid(A_raw), permuted n
__device__ __align__(16) float g_Cperm[DM * NS];           // sigmoid(C_w), permuted n
__device__ __align__(16) float g_g[DM];                    // sigmoid(gamma)
__device__ __align__(16) float g_sumC[DM];                 // sum_n sigmoid(C_w[d,n])
__device__ __align__(16) float g_U[(size_t)BB * SEQ * NS]; // X @ Bm^T, permuted n
__device__ __align__(16) float g_umin[(size_t)BB * SEQ];   // min_n U[b,s,n]
__device__ __align__(16) __nv_bfloat16 g_Ybf[(size_t)BB * SEQ * DM]; // y pre-norm, bf16

__device__ __forceinline__ float sigmoidf_(float v) {
    return 1.0f / (1.0f + expf(-v));
}

// ---------------- packed f32x2 helpers ----------------
__device__ __forceinline__ u64 pack2(float lo, float hi) {
    u64 r;
    asm("mov.b64 %0, {%1, %2};" : "=l"(r) : "f"(lo), "f"(hi));
    return r;
}
__device__ __forceinline__ void unpack2(u64 v, float& lo, float& hi) {
    asm("mov.b64 {%0, %1}, %2;" : "=f"(lo), "=f"(hi) : "l"(v));
}
__device__ __forceinline__ u64 fma2_(u64 a, u64 b, u64 c) {
    u64 r;
    asm("fma.rn.f32x2 %0, %1, %2, %3;" : "=l"(r) : "l"(a), "l"(b), "l"(c));
    return r;
}

// State update, one pair: h = min(1, h*A + u*x). Lower clip provably dead
// (u>=0, x>=0, A>0, h0=0 => h*A+u*x >= 0). min on ALU pipe.
__device__ __forceinline__ void step_pair(float& h0, float& h1, u64 u2, u64 xp, u64 a2) {
    asm("{\n\t"
        ".reg .b64 t, hp;\n\t"
        "mul.rn.f32x2 t, %2, %3;\n\t"
        "mov.b64 hp, {%0, %1};\n\t"
        "fma.rn.f32x2 hp, hp, %4, t;\n\t"
        "mov.b64 {%0, %1}, hp;\n\t"
        "}\n\t"
        : "+f"(h0), "+f"(h1) : "l"(u2), "l"(xp), "l"(a2));
    h0 = fminf(h0, 1.0f);
    h1 = fminf(h1, 1.0f);
}

__device__ __forceinline__ void dot_pair(u64& p2, float h0, float h1, u64 c2) {
    asm("{\n\t"
        ".reg .b64 hp;\n\t"
        "mov.b64 hp, {%1, %2};\n\t"
        "fma.rn.f32x2 %0, hp, %3, %0;\n\t"
        "}\n\t"
        : "+l"(p2) : "f"(h0), "f"(h1), "l"(c2));
}

// permutation: state n -> storage position, lane lp=n%4 owns n = lp + 4j,
// stored at lp*16 + j so each lane reads 16 contiguous floats (4x LDG.128)
__device__ __forceinline__ int permn(int n) { return ((n & 3) << 4) | (n >> 2); }

// ---------------- kernel 1: precompute sigmoids ----------------
__global__ void prep_kernel(const float* __restrict__ A_raw,
                            const float* __restrict__ B_w,
                            const float* __restrict__ C_w,
                            const float* __restrict__ gamma) {
    int i = blockIdx.x * 256 + threadIdx.x;
    if (i < NS * DM) {
        g_Bs[i] = sigmoidf_(B_w[i]);           // B_w is [N, D]
        int d = i >> 6, n = i & 63;            // A_raw / C_w are [D, N]
        int p = permn(n);
        g_Aperm[(d << 6) + p] = sigmoidf_(A_raw[i]);
        g_Cperm[(d << 6) + p] = sigmoidf_(C_w[i]);
    }
    if (i < DM) {
        g_g[i] = sigmoidf_(gamma[i]);
        float s = 0.0f;
        for (int n = 0; n < NS; n++) s += sigmoidf_(C_w[i * NS + n]);
        g_sumC[i] = s;    // y_d when all 64 states saturate at 1.0
    }
}

// ---------------- kernel 2: U = X @ Bs^T, double-buffered ----------------
// 64 rows x 64 cols per block, 256 threads, thread = 4 rows x 4 cols via
// f32x2 (x duplicated by pack, w consumed as natural pairs from smem).
// Two smem buffers: prefetch tile t+1 into registers while computing t.
__global__ void __launch_bounds__(256) gemm_kernel(const float* __restrict__ X) {
    __shared__ __align__(16) float Xs[2][32][68];  // k-major, padded
    __shared__ __align__(16) float Ws[2][32][68];
    int tid = threadIdx.x;
    int row0 = blockIdx.x * 64;
    int tx = tid & 15, ty = tid >> 4;
    int r0 = tid >> 3, r1 = r0 + 32, q = tid & 7;  // staging coords
    u64 acc2[4][2];
#pragma unroll
    for (int i = 0; i < 4; i++) { acc2[i][0] = 0ull; acc2[i][1] = 0ull; }

    float4 xv0, xv1, wv0, wv1;
    // prefetch tile 0
    xv0 = *(const float4*)(X + (size_t)(row0 + r0) * DM + q * 4);
    xv1 = *(const float4*)(X + (size_t)(row0 + r1) * DM + q * 4);
    wv0 = *(const float4*)(g_Bs + (size_t)r0 * DM + q * 4);
    wv1 = *(const float4*)(g_Bs + (size_t)r1 * DM + q * 4);
    // store tile 0 into buf 0
    Xs[0][q * 4 + 0][r0] = xv0.x; Xs[0][q * 4 + 1][r0] = xv0.y;
    Xs[0][q * 4 + 2][r0] = xv0.z; Xs[0][q * 4 + 3][r0] = xv0.w;
    Xs[0][q * 4 + 0][r1] = xv1.x; Xs[0][q * 4 + 1][r1] = xv1.y;
    Xs[0][q * 4 + 2][r1] = xv1.z; Xs[0][q * 4 + 3][r1] = xv1.w;
    Ws[0][q * 4 + 0][r0] = wv0.x; Ws[0][q * 4 + 1][r0] = wv0.y;
    Ws[0][q * 4 + 2][r0] = wv0.z; Ws[0][q * 4 + 3][r0] = wv0.w;
    Ws[0][q * 4 + 0][r1] = wv1.x; Ws[0][q * 4 + 1][r1] = wv1.y;
    Ws[0][q * 4 + 2][r1] = wv1.z; Ws[0][q * 4 + 3][r1] = wv1.w;
    __syncthreads();

    for (int t = 0; t < 32; t++) {
        int cur = t & 1;
        if (t < 31) {   // prefetch next tile into registers (overlaps compute)
            int k0 = (t + 1) * 32;
            xv0 = *(const float4*)(X + (size_t)(row0 + r0) * DM + k0 + q * 4);
            xv1 = *(const float4*)(X + (size_t)(row0 + r1) * DM + k0 + q * 4);
            wv0 = *(const float4*)(g_Bs + (size_t)r0 * DM + k0 + q * 4);
            wv1 = *(const float4*)(g_Bs + (size_t)r1 * DM + k0 + q * 4);
        }
#pragma unroll
        for (int k = 0; k < 32; k++) {
            float4 xa = *(const float4*)&Xs[cur][k][ty * 4];
            ulonglong2 wv = *(const ulonglong2*)&Ws[cur][k][tx * 4];
            u64 xp[4] = {pack2(xa.x, xa.x), pack2(xa.y, xa.y),
                         pack2(xa.z, xa.z), pack2(xa.w, xa.w)};
#pragma unroll
            for (int i = 0; i < 4; i++) {
                acc2[i][0] = fma2_(xp[i], wv.x, acc2[i][0]);
                acc2[i][1] = fma2_(xp[i], wv.y, acc2[i][1]);
            }
        }
        if (t < 31) {   // stage prefetched tile into the other buffer
            int nb = cur ^ 1;
            Xs[nb][q * 4 + 0][r0] = xv0.x; Xs[nb][q * 4 + 1][r0] = xv0.y;
            Xs[nb][q * 4 + 2][r0] = xv0.z; Xs[nb][q * 4 + 3][r0] = xv0.w;
            Xs[nb][q * 4 + 0][r1] = xv1.x; Xs[nb][q * 4 + 1][r1] = xv1.y;
            Xs[nb][q * 4 + 2][r1] = xv1.z; Xs[nb][q * 4 + 3][r1] = xv1.w;
            Ws[nb][q * 4 + 0][r0] = wv0.x; Ws[nb][q * 4 + 1][r0] = wv0.y;
            Ws[nb][q * 4 + 2][r0] = wv0.z; Ws[nb][q * 4 + 3][r0] = wv0.w;
            Ws[nb][q * 4 + 0][r1] = wv1.x; Ws[nb][q * 4 + 1][r1] = wv1.y;
            Ws[nb][q * 4 + 2][r1] = wv1.z; Ws[nb][q * 4 + 3][r1] = wv1.w;
        }
        __syncthreads();
    }

#pragma unroll
    for (int i = 0; i < 4; i++) {
        float a0, a1, a2, a3;
        unpack2(acc2[i][0], a0, a1);
        unpack2(acc2[i][1], a2, a3);
        size_t rb = (size_t)(row0 + ty * 4 + i) * NS;
        g_U[rb + permn(tx * 4 + 0)] = a0;
        g_U[rb + permn(tx * 4 + 1)] = a1;
        g_U[rb + permn(tx * 4 + 2)] = a2;
        g_U[rb + permn(tx * 4 + 3)] = a3;
    }
}

// ---------------- kernel 2b: umin[b,s] = min_n U[b,s,n] ----------------
__global__ void __launch_bounds__(256) umin_kernel() {
    int gid = blockIdx.x * 256 + threadIdx.x;
    int row = gid >> 3, l = gid & 7;
    const float4* U4 = (const float4*)g_U;
    float4 v1 = U4[(size_t)row * 16 + l * 2];
    float4 v2 = U4[(size_t)row * 16 + l * 2 + 1];
    float m = fminf(fminf(fminf(v1.x, v1.y), fminf(v1.z, v1.w)),
                    fminf(fminf(v2.x, v2.y), fminf(v2.z, v2.w)));
    m = fminf(m, __shfl_xor_sync(0xffffffffu, m, 1, 8));
    m = fminf(m, __shfl_xor_sync(0xffffffffu, m, 2, 8));
    m = fminf(m, __shfl_xor_sync(0xffffffffu, m, 4, 8));
    if (l == 0) g_umin[row] = m;
}

// ---------------- kernel 3: chunked parallel scan, saturation fast path --
// grid (D/32, NCHUNK, B), block 128. Warp owns 8 d's (4 lanes each), lane
// owns 16 n-states. If x[b,s,d]*umin[b,s] >= 1 then EVERY state of that d
// saturates to exactly 1.0 this step (min(1, h*A + u*x) with u*x >= 1, RN
// monotone, h*A >= 0) and y_d = sum_n C[d,n]. Warp-vote: if all 8 d's
// saturate, skip the whole update. Slow path fetches u/A/C from L2.

template <bool WRITE_Y>
__device__ __forceinline__ void scan_chunk(
    int b, int s0, const float* __restrict__ xs, const float* __restrict__ ums,
    float* __restrict__ ys, float* h, bool& ones, float sumCd,
    int d, int lp, int dloc) {
#pragma unroll 4
    for (int sl = 0; sl < SCH; ++sl) {
        float xv = xs[(sl << 5) + dloc];
        float um = ums[sl];
        bool sat = (xv * um >= 1.0f);
        float yv = sumCd;
        if (!__all_sync(0xffffffffu, sat)) {
            // slow path (warp-uniform branch)
            if (ones) {
#pragma unroll
                for (int j = 0; j < 16; j++) h[j] = 1.0f;
                ones = false;
            }
            const ulonglong2* up = (const ulonglong2*)(
                g_U + (((size_t)b * SEQ + s0 + sl) << 6) + (lp << 4));
            ulonglong2 u0 = up[0], u1 = up[1], u2 = up[2], u3 = up[3];
            const ulonglong2* ap = (const ulonglong2*)(
                g_Aperm + ((size_t)d << 6) + (lp << 4));
            ulonglong2 a0 = ap[0], a1 = ap[1], a2 = ap[2], a3 = ap[3];
            u64 xp = pack2(xv, xv);
            step_pair(h[0],  h[1],  u0.x, xp, a0.x);
            step_pair(h[2],  h[3],  u0.y, xp, a0.y);
            step_pair(h[4],  h[5],  u1.x, xp, a1.x);
            step_pair(h[6],  h[7],  u1.y, xp, a1.y);
            step_pair(h[8],  h[9],  u2.x, xp, a2.x);
            step_pair(h[10], h[11], u2.y, xp, a2.y);
            step_pair(h[12], h[13], u3.x, xp, a3.x);
            step_pair(h[14], h[15], u3.y, xp, a3.y);
            if (WRITE_Y) {
                const ulonglong2* cp = (const ulonglong2*)(
                    g_Cperm + ((size_t)d << 6) + (lp << 4));
                ulonglong2 c0 = cp[0], c1 = cp[1], c2 = cp[2], c3 = cp[3];
                u64 p2 = 0ull;
                dot_pair(p2, h[0],  h[1],  c0.x);
                dot_pair(p2, h[2],  h[3],  c0.y);
                dot_pair(p2, h[4],  h[5],  c1.x);
                dot_pair(p2, h[6],  h[7],  c1.y);
                dot_pair(p2, h[8],  h[9],  c2.x);
                dot_pair(p2, h[10], h[11], c2.y);
                dot_pair(p2, h[12], h[13], c3.x);
                dot_pair(p2, h[14], h[15], c3.y);
                float plo, phi;
                unpack2(p2, plo, phi);
                float p = plo + phi;
                p += __shfl_xor_sync(0xffffffffu, p, 1, 4);
                p += __shfl_xor_sync(0xffffffffu, p, 2, 4);
                yv = p;
            }
        } else {
            ones = true;   // h == all-ones, materialized lazily
        }
        if (WRITE_Y && lp == 0) ys[(sl << 5) + dloc] = yv;
    }
}

__global__ void __launch_bounds__(128, 8) scan_kernel(const float* __restrict__ X,
                                                      float* __restrict__ Hout) {
    __shared__ __align__(16) float xs[SCH * 32];   // x chunk for this CTA's 32 d
    __shared__ __align__(16) float ys[SCH * 32];   // y chunk (pre-normalization)
    __shared__ __align__(16) float ums[SCH];       // umin chunk

    int b = blockIdx.z;
    int c = blockIdx.y;
    int dbase = blockIdx.x << 5;
    int tid = threadIdx.x;
    int warp = tid >> 5, lane = tid & 31;
    int grp = lane >> 2, lp = lane & 3;
    int dloc = (warp << 3) | grp;    // 0..31
    int d = dbase + dloc;

    float h[16];
    bool ones = false;
#pragma unroll
    for (int j = 0; j < 16; j++) h[j] = 0.0f;
    float sumCd = g_sumC[d];

    const size_t xbase = (size_t)b * SEQ * DM;
    const int s_out0 = c * CHUNK;
    const int s_begin = (c == 0) ? 0 : s_out0 - WARM;
    const int s_end = s_out0 + CHUNK;

    for (int s0 = s_begin; s0 < s_end; s0 += SCH) {
        __syncthreads();
        {   // stage x chunk: 64 steps x 32 d (coalesced)
#pragma unroll
            for (int i = 0; i < 4; i++) {
                int idx = tid + (i << 7);
                int sl = idx >> 3, q = idx & 7;
                ((float4*)xs)[idx] =
                    *(const float4*)(X + xbase + (size_t)(s0 + sl) * DM + dbase + (q << 2));
            }
            if (tid < 16)
                ((float4*)ums)[tid] =
                    ((const float4*)(g_umin + (size_t)b * SEQ + s0))[tid];
        }
        __syncthreads();

        bool writey = (s0 >= s_out0);
        if (writey)
            scan_chunk<true>(b, s0, xs, ums, ys, h, ones, sumCd, d, lp, dloc);
        else
            scan_chunk<false>(b, s0, xs, ums, ys, h, ones, sumCd, d, lp, dloc);

        if (writey) {
            __syncthreads();
            // dump y chunk as bf16 (coalesced) into g_Ybf
#pragma unroll
            for (int i = 0; i < 4; i++) {
                int idx = tid + (i << 7);
                int sl = idx >> 3, q = idx & 7;
                float4 v = ((float4*)ys)[idx];
                __nv_bfloat162 p0 = __floats2bfloat162_rn(v.x, v.y);
                __nv_bfloat162 p1 = __floats2bfloat162_rn(v.z, v.w);
                uint2 pk;
                pk.x = *(u32*)&p0;
                pk.y = *(u32*)&p1;
                *(uint2*)(g_Ybf + ((size_t)b * SEQ + s0 + sl) * DM + dbase + (q << 2)) = pk;
            }
        }
    }

    if (Hout && c == NCHUNK - 1) {   // h_final [B, D, N], lane lp owns n = lp + 4j
#pragma unroll
        for (int j = 0; j < 16; j++) {
            float hv = ones ? 1.0f : h[j];
            Hout[(((size_t)b * DM + d) << 6) + lp + (j << 2)] = hv;
        }
    }
}

// ---------------- kernel 4: normalize + residual + clip ----------------
__global__ void __launch_bounds__(256) finalize_kernel(const float* __restrict__ X,
                                                       float* __restrict__ out) {
    size_t row = blockIdx.x;   // b*SEQ + s
    int tid = threadIdx.x;
    uint2 yv = *(const uint2*)(g_Ybf + row * DM + tid * 4);
    __nv_bfloat162 y0 = *(__nv_bfloat162*)&yv.x;
    __nv_bfloat162 y1 = *(__nv_bfloat162*)&yv.y;
    float2 f0 = __bfloat1622float2(y0);
    float2 f1 = __bfloat1622float2(y1);
    float4 v = make_float4(f0.x, f0.y, f1.x, f1.y);
    float ps = v.x + v.y + v.z + v.w;
#pragma unroll
    for (int o = 16; o; o >>= 1) ps += __shfl_xor_sync(0xffffffffu, ps, o);
    __shared__ float wsum[8];
    if ((tid & 31) == 0) wsum[tid >> 5] = ps;
    __syncthreads();
    float tot = 0.0f;
#pragma unroll
    for (int w = 0; w < 8; w++) tot += wsum[w];
    float inv = 1.0f / (tot + 1e-6f);
    float4 xv = ((const float4*)(X + row * DM))[tid];
    float4 gv = ((const float4*)g_g)[tid];
    float4 r;
    r.x = __saturatef(fmaf(v.x * gv.x, inv, xv.x));
    r.y = __saturatef(fmaf(v.y * gv.y, inv, xv.y));
    r.z = __saturatef(fmaf(v.z * gv.z, inv, xv.z));
    r.w = __saturatef(fmaf(v.w * gv.w, inv, xv.w));
    ((float4*)(out + row * DM))[tid] = r;
}

// ---------------- launch ----------------
extern "C" void kernel_launch(void* const* d_in, const int* in_sizes, int n_in,
                              void* d_out, int out_size) {
    const float* x     = (const float*)d_in[0];
    const float* A_raw = (const float*)d_in[1];
    const float* B_w   = (const float*)d_in[2];
    const float* C_w   = (const float*)d_in[3];
    const float* gamma = (const float*)d_in[4];
    float* out = (float*)d_out;

    const size_t Y_ELEMS = (size_t)BB * SEQ * DM;       // 33,554,432
    const size_t H_ELEMS = (size_t)BB * DM * NS;        // 524,288
    float* hout = ((size_t)out_size >= Y_ELEMS + H_ELEMS) ? (out + Y_ELEMS) : nullptr;

    prep_kernel<<<256, 256>>>(A_raw, B_w, C_w, gamma);
    gemm_kernel<<<(BB * SEQ) / 64, 256>>>(x);
    umin_kernel<<<(BB * SEQ * 8) / 256, 256>>>();
    scan_kernel<<<dim3(DM / 32, NCHUNK, BB), 128>>>(x, hout);
    finalize_kernel<<<BB * SEQ, 256>>>(x, out);
}

// round 13
// speedup vs baseline: 1.2615x; 1.1395x over previous
#include <cuda_runtime.h>
#include <cuda_bf16.h>
#include <math.h>

#define BB 8
#define SEQ 4096
#define DM 1024
#define NS 64
#define SCH 64          // scan steps per smem chunk
#define CHUNK 512       // sequence chunk per CTA (parallel-in-time)
#define WARM 64         // warmup steps (state error <= 0.7311^64 ~ 2e-9)
#define NCHUNK (SEQ / CHUNK)

typedef unsigned long long u64;
typedef unsigned int u32;

// ---------------- static scratch (no allocations allowed) ----------------
__device__ __align__(16) float g_Bs[NS * DM];              // sigmoid(B_w), [N, D]
__device__ __align__(16) float g_Aperm[DM * NS];           // sigmoid(A_raw), permuted n
__device__ __align__(16) float g_Cperm[DM * NS];           // sigmoid(C_w), permuted n
__device__ __align__(16) float g_g[DM];                    // sigmoid(gamma)
__device__ __align__(16) float g_sumC[DM];                 // sum_n sigmoid(C_w[d,n])
__device__ __align__(16) float g_U[(size_t)BB * SEQ * NS]; // X @ Bm^T, permuted n
__device__ __align__(16) float g_umin[(size_t)BB * SEQ];   // min_n U[b,s,n]
__device__ __align__(16) __nv_bfloat16 g_Ybf[(size_t)BB * SEQ * DM]; // y pre-norm, bf16

__device__ __forceinline__ float sigmoidf_(float v) {
    return 1.0f / (1.0f + expf(-v));
}

// ---------------- packed f32x2 helpers ----------------
__device__ __forceinline__ u64 pack2(float lo, float hi) {
    u64 r;
    asm("mov.b64 %0, {%1, %2};" : "=l"(r) : "f"(lo), "f"(hi));
    return r;
}
__device__ __forceinline__ void unpack2(u64 v, float& lo, float& hi) {
    asm("mov.b64 {%0, %1}, %2;" : "=f"(lo), "=f"(hi) : "l"(v));
}
__device__ __forceinline__ u64 fma2_(u64 a, u64 b, u64 c) {
    u64 r;
    asm("fma.rn.f32x2 %0, %1, %2, %3;" : "=l"(r) : "l"(a), "l"(b), "l"(c));
    return r;
}

// State update, one pair: h = min(1, h*A + u*x). Lower clip provably dead
// (u>=0, x>=0, A>0, h0=0 => h*A+u*x >= 0). min on ALU pipe.
__device__ __forceinline__ void step_pair(float& h0, float& h1, u64 u2, u64 xp, u64 a2) {
    asm("{\n\t"
        ".reg .b64 t, hp;\n\t"
        "mul.rn.f32x2 t, %2, %3;\n\t"
        "mov.b64 hp, {%0, %1};\n\t"
        "fma.rn.f32x2 hp, hp, %4, t;\n\t"
        "mov.b64 {%0, %1}, hp;\n\t"
        "}\n\t"
        : "+f"(h0), "+f"(h1) : "l"(u2), "l"(xp), "l"(a2));
    h0 = fminf(h0, 1.0f);
    h1 = fminf(h1, 1.0f);
}

__device__ __forceinline__ void dot_pair(u64& p2, float h0, float h1, u64 c2) {
    asm("{\n\t"
        ".reg .b64 hp;\n\t"
        "mov.b64 hp, {%1, %2};\n\t"
        "fma.rn.f32x2 %0, hp, %3, %0;\n\t"
        "}\n\t"
        : "+l"(p2) : "f"(h0), "f"(h1), "l"(c2));
}

// permutation: state n -> storage position, lane lp=n%4 owns n = lp + 4j,
// stored at lp*16 + j so each lane reads 16 contiguous floats (4x LDG.128)
__device__ __forceinline__ int permn(int n) { return ((n & 3) << 4) | (n >> 2); }

// ---------------- kernel 1: precompute sigmoids ----------------
__global__ void prep_kernel(const float* __restrict__ A_raw,
                            const float* __restrict__ B_w,
                            const float* __restrict__ C_w,
                            const float* __restrict__ gamma) {
    int i = blockIdx.x * 256 + threadIdx.x;
    if (i < NS * DM) {
        g_Bs[i] = sigmoidf_(B_w[i]);           // B_w is [N, D]
        int d = i >> 6, n = i & 63;            // A_raw / C_w are [D, N]
        int p = permn(n);
        g_Aperm[(d << 6) + p] = sigmoidf_(A_raw[i]);
        g_Cperm[(d << 6) + p] = sigmoidf_(C_w[i]);
    }
    if (i < DM) {
        g_g[i] = sigmoidf_(gamma[i]);
        float s = 0.0f;
        for (int n = 0; n < NS; n++) s += sigmoidf_(C_w[i * NS + n]);
        g_sumC[i] = s;    // y_d when all 64 states saturate at 1.0
    }
}

// ---------------- kernel 2: U = X @ Bs^T, double-buffered ----------------
__global__ void __launch_bounds__(256) gemm_kernel(const float* __restrict__ X) {
    __shared__ __align__(16) float Xs[2][32][68];  // k-major, padded
    __shared__ __align__(16) float Ws[2][32][68];
    int tid = threadIdx.x;
    int row0 = blockIdx.x * 64;
    int tx = tid & 15, ty = tid >> 4;
    int r0 = tid >> 3, r1 = r0 + 32, q = tid & 7;  // staging coords
    u64 acc2[4][2];
#pragma unroll
    for (int i = 0; i < 4; i++) { acc2[i][0] = 0ull; acc2[i][1] = 0ull; }

    float4 xv0, xv1, wv0, wv1;
    xv0 = *(const float4*)(X + (size_t)(row0 + r0) * DM + q * 4);
    xv1 = *(const float4*)(X + (size_t)(row0 + r1) * DM + q * 4);
    wv0 = *(const float4*)(g_Bs + (size_t)r0 * DM + q * 4);
    wv1 = *(const float4*)(g_Bs + (size_t)r1 * DM + q * 4);
    Xs[0][q * 4 + 0][r0] = xv0.x; Xs[0][q * 4 + 1][r0] = xv0.y;
    Xs[0][q * 4 + 2][r0] = xv0.z; Xs[0][q * 4 + 3][r0] = xv0.w;
    Xs[0][q * 4 + 0][r1] = xv1.x; Xs[0][q * 4 + 1][r1] = xv1.y;
    Xs[0][q * 4 + 2][r1] = xv1.z; Xs[0][q * 4 + 3][r1] = xv1.w;
    Ws[0][q * 4 + 0][r0] = wv0.x; Ws[0][q * 4 + 1][r0] = wv0.y;
    Ws[0][q * 4 + 2][r0] = wv0.z; Ws[0][q * 4 + 3][r0] = wv0.w;
    Ws[0][q * 4 + 0][r1] = wv1.x; Ws[0][q * 4 + 1][r1] = wv1.y;
    Ws[0][q * 4 + 2][r1] = wv1.z; Ws[0][q * 4 + 3][r1] = wv1.w;
    __syncthreads();

    for (int t = 0; t < 32; t++) {
        int cur = t & 1;
        if (t < 31) {   // prefetch next tile into registers (overlaps compute)
            int k0 = (t + 1) * 32;
            xv0 = *(const float4*)(X + (size_t)(row0 + r0) * DM + k0 + q * 4);
            xv1 = *(const float4*)(X + (size_t)(row0 + r1) * DM + k0 + q * 4);
            wv0 = *(const float4*)(g_Bs + (size_t)r0 * DM + k0 + q * 4);
            wv1 = *(const float4*)(g_Bs + (size_t)r1 * DM + k0 + q * 4);
        }
#pragma unroll
        for (int k = 0; k < 32; k++) {
            float4 xa = *(const float4*)&Xs[cur][k][ty * 4];
            ulonglong2 wv = *(const ulonglong2*)&Ws[cur][k][tx * 4];
            u64 xp[4] = {pack2(xa.x, xa.x), pack2(xa.y, xa.y),
                         pack2(xa.z, xa.z), pack2(xa.w, xa.w)};
#pragma unroll
            for (int i = 0; i < 4; i++) {
                acc2[i][0] = fma2_(xp[i], wv.x, acc2[i][0]);
                acc2[i][1] = fma2_(xp[i], wv.y, acc2[i][1]);
            }
        }
        if (t < 31) {
            int nb = cur ^ 1;
            Xs[nb][q * 4 + 0][r0] = xv0.x; Xs[nb][q * 4 + 1][r0] = xv0.y;
            Xs[nb][q * 4 + 2][r0] = xv0.z; Xs[nb][q * 4 + 3][r0] = xv0.w;
            Xs[nb][q * 4 + 0][r1] = xv1.x; Xs[nb][q * 4 + 1][r1] = xv1.y;
            Xs[nb][q * 4 + 2][r1] = xv1.z; Xs[nb][q * 4 + 3][r1] = xv1.w;
            Ws[nb][q * 4 + 0][r0] = wv0.x; Ws[nb][q * 4 + 1][r0] = wv0.y;
            Ws[nb][q * 4 + 2][r0] = wv0.z; Ws[nb][q * 4 + 3][r0] = wv0.w;
            Ws[nb][q * 4 + 0][r1] = wv1.x; Ws[nb][q * 4 + 1][r1] = wv1.y;
            Ws[nb][q * 4 + 2][r1] = wv1.z; Ws[nb][q * 4 + 3][r1] = wv1.w;
        }
        __syncthreads();
    }

#pragma unroll
    for (int i = 0; i < 4; i++) {
        float a0, a1, a2, a3;
        unpack2(acc2[i][0], a0, a1);
        unpack2(acc2[i][1], a2, a3);
        size_t rb = (size_t)(row0 + ty * 4 + i) * NS;
        g_U[rb + permn(tx * 4 + 0)] = a0;
        g_U[rb + permn(tx * 4 + 1)] = a1;
        g_U[rb + permn(tx * 4 + 2)] = a2;
        g_U[rb + permn(tx * 4 + 3)] = a3;
    }
}

// ---------------- kernel 2b: umin[b,s] = min_n U[b,s,n] ----------------
__global__ void __launch_bounds__(256) umin_kernel() {
    int gid = blockIdx.x * 256 + threadIdx.x;
    int row = gid >> 3, l = gid & 7;
    const float4* U4 = (const float4*)g_U;
    float4 v1 = U4[(size_t)row * 16 + l * 2];
    float4 v2 = U4[(size_t)row * 16 + l * 2 + 1];
    float m = fminf(fminf(fminf(v1.x, v1.y), fminf(v1.z, v1.w)),
                    fminf(fminf(v2.x, v2.y), fminf(v2.z, v2.w)));
    m = fminf(m, __shfl_xor_sync(0xffffffffu, m, 1, 8));
    m = fminf(m, __shfl_xor_sync(0xffffffffu, m, 2, 8));
    m = fminf(m, __shfl_xor_sync(0xffffffffu, m, 4, 8));
    if (l == 0) g_umin[row] = m;
}

// ---------------- kernel 3 helpers: full (slow) step ----------------
template <bool WRITE_Y>
__device__ __forceinline__ void slow_step(
    int b, int s, const float* __restrict__ xs, float* __restrict__ ys,
    float* h, int sl, int d, int lp, int dloc) {
    float xv = xs[(sl << 5) + dloc];
    const ulonglong2* up = (const ulonglong2*)(
        g_U + (((size_t)b * SEQ + s) << 6) + (lp << 4));
    ulonglong2 u0 = up[0], u1 = up[1], u2 = up[2], u3 = up[3];
    const ulonglong2* ap = (const ulonglong2*)(
        g_Aperm + ((size_t)d << 6) + (lp << 4));
    ulonglong2 a0 = ap[0], a1 = ap[1], a2 = ap[2], a3 = ap[3];
    u64 xp = pack2(xv, xv);
    step_pair(h[0],  h[1],  u0.x, xp, a0.x);
    step_pair(h[2],  h[3],  u0.y, xp, a0.y);
    step_pair(h[4],  h[5],  u1.x, xp, a1.x);
    step_pair(h[6],  h[7],  u1.y, xp, a1.y);
    step_pair(h[8],  h[9],  u2.x, xp, a2.x);
    step_pair(h[10], h[11], u2.y, xp, a2.y);
    step_pair(h[12], h[13], u3.x, xp, a3.x);
    step_pair(h[14], h[15], u3.y, xp, a3.y);
    if (WRITE_Y) {
        const ulonglong2* cp = (const ulonglong2*)(
            g_Cperm + ((size_t)d << 6) + (lp << 4));
        ulonglong2 c0 = cp[0], c1 = cp[1], c2 = cp[2], c3 = cp[3];
        u64 p2 = 0ull;
        dot_pair(p2, h[0],  h[1],  c0.x);
        dot_pair(p2, h[2],  h[3],  c0.y);
        dot_pair(p2, h[4],  h[5],  c1.x);
        dot_pair(p2, h[6],  h[7],  c1.y);
        dot_pair(p2, h[8],  h[9],  c2.x);
        dot_pair(p2, h[10], h[11], c2.y);
        dot_pair(p2, h[12], h[13], c3.x);
        dot_pair(p2, h[14], h[15], c3.y);
        float plo, phi;
        unpack2(p2, plo, phi);
        float p = plo + phi;
        p += __shfl_xor_sync(0xffffffffu, p, 1, 4);
        p += __shfl_xor_sync(0xffffffffu, p, 2, 4);
        if (lp == 0) ys[(sl << 5) + dloc] = p;
    }
}

// ---------------- kernel 3: chunked scan, mask-staged saturation ----------
// grid (D/32, NCHUNK, B), block 128. Warp owns 8 d's (4 lanes each), lane
// owns 16 n-states. x*umin >= 1 forces ALL states of a d to exactly 1.0
// (RN monotone, h*A >= 0) and y_d = sumC. The saturation test runs in the
// STAGING phase (values already in registers); each (sl, q-group) result
// is one smem byte. After the sync each warp builds its 64-bit mask with
// 2 LDS.64 + 2 ballots, prefilled ys supplies y for saturated steps, and
// the scan loop visits only the ~3% slow bits via __ffs.
__global__ void __launch_bounds__(128, 8) scan_kernel(const float* __restrict__ X,
                                                      float* __restrict__ Hout) {
    __shared__ __align__(16) float xs[SCH * 32];        // x chunk [sl][dloc]
    __shared__ __align__(16) float ys[SCH * 32];        // y chunk (pre-norm)
    __shared__ __align__(8) unsigned char satb[SCH * 8]; // [sl][q] saturation byte

    int b = blockIdx.z;
    int c = blockIdx.y;
    int dbase = blockIdx.x << 5;
    int tid = threadIdx.x;
    int warp = tid >> 5, lane = tid & 31;
    int grp = lane >> 2, lp = lane & 3;
    int dloc = (warp << 3) | grp;    // 0..31
    int d = dbase + dloc;
    int qme = tid & 7;               // staging column group

    float h[16];
    bool ones = false;
#pragma unroll
    for (int j = 0; j < 16; j++) h[j] = 0.0f;
    float4 sumC4 = *(const float4*)(g_sumC + dbase + (qme << 2));

    const size_t xbase = (size_t)b * SEQ * DM;
    const int s_out0 = c * CHUNK;
    const int s_begin = (c == 0) ? 0 : s_out0 - WARM;
    const int s_end = s_out0 + CHUNK;

    for (int s0 = s_begin; s0 < s_end; s0 += SCH) {
        bool writey = (s0 >= s_out0);
        __syncthreads();                       // prev chunk fully consumed
#pragma unroll
        for (int i = 0; i < 4; i++) {          // stage + test (one owner per (sl,q))
            int idx = tid + (i << 7);
            int sl = idx >> 3;
            float4 xv = *(const float4*)(X + xbase + (size_t)(s0 + sl) * DM +
                                         dbase + (qme << 2));
            float um = __ldg(g_umin + (size_t)b * SEQ + s0 + sl);
            bool bb = (xv.x * um >= 1.0f) & (xv.y * um >= 1.0f) &
                      (xv.z * um >= 1.0f) & (xv.w * um >= 1.0f);
            ((float4*)xs)[idx] = xv;
            if (writey) ((float4*)ys)[idx] = sumC4;
            satb[sl * 8 + qme] = bb ? 1 : 0;
        }
        __syncthreads();                       // xs, ys prefill, satb visible

        // build this warp's 64-bit saturation mask: lane l checks sl=l, sl=32+l
        const u64* sp = (const u64*)satb;
        u64 v0 = sp[lane];
        u64 v1 = sp[32 + lane];
        int sh = warp << 4;                    // bytes 2w, 2w+1
        u32 sat0 = __ballot_sync(0xffffffffu, ((v0 >> sh) & 0xFFFFull) == 0x0101ull);
        u32 sat1 = __ballot_sync(0xffffffffu, ((v1 >> sh) & 0xFFFFull) == 0x0101ull);

        u32 w0 = ~sat0, w1 = ~sat1;
        while (w0) {
            int sl = __ffs(w0) - 1;
            w0 &= w0 - 1;
            bool ps = sl ? ((sat0 >> (sl - 1)) & 1u) : ones;
            if (ps) {
#pragma unroll
                for (int j = 0; j < 16; j++) h[j] = 1.0f;
            }
            if (writey) slow_step<true>(b, s0 + sl, xs, ys, h, sl, d, lp, dloc);
            else        slow_step<false>(b, s0 + sl, xs, ys, h, sl, d, lp, dloc);
        }
        while (w1) {
            int t = __ffs(w1) - 1;
            w1 &= w1 - 1;
            int sl = 32 + t;
            bool ps = t ? ((sat1 >> (t - 1)) & 1u) : ((sat0 >> 31) & 1u);
            if (ps) {
#pragma unroll
                for (int j = 0; j < 16; j++) h[j] = 1.0f;
            }
            if (writey) slow_step<true>(b, s0 + sl, xs, ys, h, sl, d, lp, dloc);
            else        slow_step<false>(b, s0 + sl, xs, ys, h, sl, d, lp, dloc);
        }
        ones = ((sat1 >> 31) & 1u) != 0;

        if (writey) {
            __syncthreads();
            // dump y chunk as bf16 (coalesced) into g_Ybf
#pragma unroll
            for (int i = 0; i < 4; i++) {
                int idx = tid + (i << 7);
                int sl = idx >> 3, q = idx & 7;
                float4 v = ((float4*)ys)[idx];
                __nv_bfloat162 p0 = __floats2bfloat162_rn(v.x, v.y);
                __nv_bfloat162 p1 = __floats2bfloat162_rn(v.z, v.w);
                uint2 pk;
                pk.x = *(u32*)&p0;
                pk.y = *(u32*)&p1;
                *(uint2*)(g_Ybf + ((size_t)b * SEQ + s0 + sl) * DM + dbase + (q << 2)) = pk;
            }
        }
    }

    if (Hout && c == NCHUNK - 1) {   // h_final [B, D, N], lane lp owns n = lp + 4j
#pragma unroll
        for (int j = 0; j < 16; j++) {
            float hv = ones ? 1.0f : h[j];
            Hout[(((size_t)b * DM + d) << 6) + lp + (j << 2)] = hv;
        }
    }
}

// ---------------- kernel 4: normalize + residual + clip ----------------
__global__ void __launch_bounds__(256) finalize_kernel(const float* __restrict__ X,
                                                       float* __restrict__ out) {
    size_t row = blockIdx.x;   // b*SEQ + s
    int tid = threadIdx.x;
    uint2 yv = *(const uint2*)(g_Ybf + row * DM + tid * 4);
    __nv_bfloat162 y0 = *(__nv_bfloat162*)&yv.x;
    __nv_bfloat162 y1 = *(__nv_bfloat162*)&yv.y;
    float2 f0 = __bfloat1622float2(y0);
    float2 f1 = __bfloat1622float2(y1);
    float4 v = make_float4(f0.x, f0.y, f1.x, f1.y);
    float ps = v.x + v.y + v.z + v.w;
#pragma unroll
    for (int o = 16; o; o >>= 1) ps += __shfl_xor_sync(0xffffffffu, ps, o);
    __shared__ float wsum[8];
    if ((tid & 31) == 0) wsum[tid >> 5] = ps;
    __syncthreads();
    float tot = 0.0f;
#pragma unroll
    for (int w = 0; w < 8; w++) tot += wsum[w];
    float inv = 1.0f / (tot + 1e-6f);
    float4 xv = ((const float4*)(X + row * DM))[tid];
    float4 gv = ((const float4*)g_g)[tid];
    float4 r;
    r.x = __saturatef(fmaf(v.x * gv.x, inv, xv.x));
    r.y = __saturatef(fmaf(v.y * gv.y, inv, xv.y));
    r.z = __saturatef(fmaf(v.z * gv.z, inv, xv.z));
    r.w = __saturatef(fmaf(v.w * gv.w, inv, xv.w));
    ((float4*)(out + row * DM))[tid] = r;
}

// ---------------- launch ----------------
extern "C" void kernel_launch(void* const* d_in, const int* in_sizes, int n_in,
                              void* d_out, int out_size) {
    const float* x     = (const float*)d_in[0];
    const float* A_raw = (const float*)d_in[1];
    const float* B_w   = (const float*)d_in[2];
    const float* C_w   = (const float*)d_in[3];
    const float* gamma = (const float*)d_in[4];
    float* out = (float*)d_out;

    const size_t Y_ELEMS = (size_t)BB * SEQ * DM;       // 33,554,432
    const size_t H_ELEMS = (size_t)BB * DM * NS;        // 524,288
    float* hout = ((size_t)out_size >= Y_ELEMS + H_ELEMS) ? (out + Y_ELEMS) : nullptr;

    prep_kernel<<<256, 256>>>(A_raw, B_w, C_w, gamma);
    gemm_kernel<<<(BB * SEQ) / 64, 256>>>(x);
    umin_kernel<<<(BB * SEQ * 8) / 256, 256>>>();
    scan_kernel<<<dim3(DM / 32, NCHUNK, BB), 128>>>(x, hout);
    finalize_kernel<<<BB * SEQ, 256>>>(x, out);
}